// round 14
// baseline (speedup 1.0000x reference)
#include <cuda_runtime.h>
#include <cuda_fp16.h>
#include <math.h>
#include <stdint.h>

#define CB 16
#define CS 512
#define CN 321
#define CD 512
#define CDF 2048
#define CP 96
#define KPAD 384
#define CBN (CB*CN)
#define DD ((size_t)CD*CD)
#define BND ((size_t)CBN*CD)
#define BNMD ((size_t)CBN*4*CD)
#define QAPAD ((size_t)CB*4*CD*KPAD)
#define ATT ((size_t)CB*4*CD*CD)
#define ALPHA_ 0.3f

// ---------------- fp32 workspace ----------------
#define O_H    ((size_t)0)
#define O_MEAN (O_H + BND)
#define O_STD  (O_MEAN + CBN)
#define O_BQKV (O_STD + CBN)          /* 2*3*CD */
#define O_DOT  (O_BQKV + 2*3*CD)
#define O_AO   (O_DOT + ATT)
#define O_ATT  (O_AO + BNMD)
#define O_X1   (O_ATT + BND)
#define O_Y2   (O_X1 + BND)
#define O_DEC  (O_Y2 + BND)
#define WS_TOTAL (O_DEC + (size_t)CBN*CP)
__device__ float g_ws[WS_TOTAL];

// ---------------- fp16 workspace ----------------
#define H_XT   ((size_t)0)
#define H_COEF (H_XT + BND)
#define H_QKV  (H_COEF + BNMD)              /* [b][n][m][1536] */
#define H_QA   (H_QKV + (size_t)CBN*4*1536)
#define H_KA   (H_QA + QAPAD)
#define H_PROB (H_KA + QAPAD)
#define H_REC  (H_PROB + ATT)
#define H_X1   (H_REC + BND)
#define H_FF   (H_X1 + BND)
#define H_WTS  (H_FF + (size_t)CBN*CDF)
/* weight sub-offsets inside H_WTS */
#define W_EMB  ((size_t)0)                  /* CD*CS */
#define W_QKV  (W_EMB + (size_t)CD*CS)      /* [l][3][D][D] = 6*DD */
#define W_WO   (W_QKV + 6*DD)               /* 2*DD */
#define W_W1   (W_WO + 2*DD)                /* 2*CDF*CD */
#define W_W2   (W_W1 + (size_t)2*CDF*CD)
#define W_PW   (W_W2 + (size_t)2*CDF*CD)    /* CP*CD */
#define W_TOTAL (W_PW + (size_t)CP*CD)
#define HW_TOTAL (H_WTS + W_TOTAL)
__device__ __align__(16) __half g_hws[HW_TOTAL];

// ---------------- helpers ----------------
__device__ __forceinline__ uint32_t smem_u32(const void* p) {
    uint32_t a;
    asm("{ .reg .u64 t; cvta.to.shared.u64 t, %1; cvt.u32.u64 %0, t; }" : "=r"(a) : "l"(p));
    return a;
}
__device__ __forceinline__ void cp16(uint32_t dst, const void* src, int sz) {
    asm volatile("cp.async.cg.shared.global [%0], [%1], 16, %2;"
                 :: "r"(dst), "l"(src), "r"(sz));
}
__device__ __forceinline__ void cp_commit() { asm volatile("cp.async.commit_group;" ::: "memory"); }

#define ASTRIDE 72                    /* halves; 144B pitch -> LDSM conflict-free */

// async load ROWS x 64 halves of a K-chunk, zero-pad rows >= rows (NT=128 threads)
template<int ROWS>
__device__ __forceinline__ void load_chunk(const __half* __restrict__ g, int rows, int ld,
                                           int k0, uint32_t smbase, int tid) {
    #pragma unroll
    for (int i = 0; i < ROWS / 16; i++) {
        int idx = tid + i * 128;
        int r = idx >> 3, c = idx & 7;
        int ok = r < rows;
        const __half* src = g + (long long)(ok ? r : 0) * ld + k0 + c * 8;
        cp16(smbase + (uint32_t)(r * ASTRIDE + c * 8) * 2u, src, ok ? 16 : 0);
    }
}

#define SMEM_128 (3*(128+128)*ASTRIDE*2)   /* 110592 */
#define SMEM_64  (2*( 64+128)*ASTRIDE*2)   /* 55296  */

// ============ generic batched NT GEMM via mma.sync fp16 + ldmatrix ============
// C[row,col] = sum_k A[row,k]*B[col,k] (+bias[col])
// act bit0 = gelu, bit1 = fp16 output (C as __half*)
// 128 threads, 4 warps in 2x2; warp tile (WM*16) x 64; BM = WM*32.
template<int BM, int WM, int NSTAGE>
__global__ __launch_bounds__(128, (BM == 64) ? 4 : 2) void gemm_tc(
    const __half* __restrict__ A, const __half* __restrict__ Bm,
    float* __restrict__ C, const float* __restrict__ bias,
    int M, int Nn, int Kd, int lda, int ldb,
    long long ldcr, long long ldcc, int bdiv,
    long long sAh, long long sAl, long long sBh, long long sBl,
    long long sCh, long long sCl, int act)
{
    constexpr int WR = BM / (WM * 16);                // 2
    constexpr int STAGE_B = (BM + 128) * ASTRIDE * 2; // bytes per stage
    extern __shared__ __half smh[];
    const int tid = threadIdx.x;
    const int wid = tid >> 5, lane = tid & 31;
    const int gid = lane >> 2, tig = lane & 3;
    const int wr = wid % WR, wc = wid / WR;

    int z = blockIdx.z;
    int zh = z / bdiv, zl = z % bdiv;
    A  += zh * sAh + zl * sAl;
    Bm += zh * sBh + zl * sBl;
    long long coff = zh * sCh + zl * sCl;

    int m0 = blockIdx.x * BM, n0 = blockIdx.y * 128;
    int mrem = M - m0, nrem = Nn - n0;
    const __half* Ag = A + (long long)m0 * lda;
    const __half* Bg = Bm + (long long)n0 * ldb;

    uint32_t smb = smem_u32(smh);

    // ldmatrix per-lane row offsets (halves)
    const int aRow = (wr * (WM * 16) + (lane & 15)) * ASTRIDE + (lane >> 4) * 8;
    const int mID = lane >> 3, rID = lane & 7;
    const int bRow = (((mID >> 1) << 3) + rID) * ASTRIDE + (mID & 1) * 8;
    const int bColBase = wc * 64;

    float c[WM][8][4];
    #pragma unroll
    for (int i = 0; i < WM; i++)
        #pragma unroll
        for (int j = 0; j < 8; j++)
            #pragma unroll
            for (int r = 0; r < 4; r++) c[i][j][r] = 0.f;

    const int NC = Kd >> 6;   // K chunks of 64

    #pragma unroll
    for (int s = 0; s < NSTAGE - 1; s++) {
        if (s < NC) {
            load_chunk<BM>(Ag, mrem, lda, s << 6, smb + s * STAGE_B, tid);
            load_chunk<128>(Bg, nrem, ldb, s << 6, smb + s * STAGE_B + BM * ASTRIDE * 2, tid);
        }
        cp_commit();
    }

    for (int ch = 0; ch < NC; ch++) {
        asm volatile("cp.async.wait_group %0;" :: "n"(NSTAGE - 2));
        __syncthreads();
        int pf = ch + NSTAGE - 1;
        if (pf < NC) {
            int s = pf % NSTAGE;
            load_chunk<BM>(Ag, mrem, lda, pf << 6, smb + s * STAGE_B, tid);
            load_chunk<128>(Bg, nrem, ldb, pf << 6, smb + s * STAGE_B + BM * ASTRIDE * 2, tid);
        }
        cp_commit();

        int cs = ch % NSTAGE;
        uint32_t aB = smb + cs * STAGE_B;
        uint32_t bB = aB + BM * ASTRIDE * 2 + (uint32_t)(bColBase * ASTRIDE) * 2u;

        #pragma unroll
        for (int ks = 0; ks < 4; ks++) {
            int kc = ks << 4;
            uint32_t a[WM][4], b[8][2];
            #pragma unroll
            for (int i = 0; i < WM; i++) {
                uint32_t ad = aB + (uint32_t)(aRow + i * 16 * ASTRIDE + kc) * 2u;
                asm volatile("ldmatrix.sync.aligned.m8n8.x4.shared.b16 {%0,%1,%2,%3}, [%4];"
                    : "=r"(a[i][0]), "=r"(a[i][1]), "=r"(a[i][2]), "=r"(a[i][3]) : "r"(ad));
            }
            #pragma unroll
            for (int jp = 0; jp < 4; jp++) {
                uint32_t bd = bB + (uint32_t)(bRow + jp * 16 * ASTRIDE + kc) * 2u;
                asm volatile("ldmatrix.sync.aligned.m8n8.x4.shared.b16 {%0,%1,%2,%3}, [%4];"
                    : "=r"(b[2*jp][0]), "=r"(b[2*jp][1]),
                      "=r"(b[2*jp+1][0]), "=r"(b[2*jp+1][1]) : "r"(bd));
            }
            #pragma unroll
            for (int i = 0; i < WM; i++)
                #pragma unroll
                for (int j = 0; j < 8; j++) {
                    asm volatile(
                        "mma.sync.aligned.m16n8k16.row.col.f32.f16.f16.f32 "
                        "{%0,%1,%2,%3}, {%4,%5,%6,%7}, {%8,%9}, {%0,%1,%2,%3};"
                        : "+f"(c[i][j][0]), "+f"(c[i][j][1]),
                          "+f"(c[i][j][2]), "+f"(c[i][j][3])
                        : "r"(a[i][0]), "r"(a[i][1]), "r"(a[i][2]), "r"(a[i][3]),
                          "r"(b[j][0]), "r"(b[j][1]));
                }
        }
    }

    // epilogue
    const bool vec = (ldcc == 1);
    #pragma unroll
    for (int i = 0; i < WM; i++) {
        int rbase = wr * (WM * 16) + i * 16 + gid;
        #pragma unroll
        for (int half = 0; half < 2; half++) {
            int rloc = rbase + half * 8;
            if (rloc >= mrem) continue;
            long long row = m0 + rloc;
            #pragma unroll
            for (int j = 0; j < 8; j++) {
                int cloc = bColBase + j * 8 + tig * 2;
                bool ok0 = cloc < nrem, ok1 = cloc + 1 < nrem;
                if (!ok0) continue;
                int col = n0 + cloc;
                float v0 = c[i][j][half * 2], v1 = c[i][j][half * 2 + 1];
                if (bias) { v0 += bias[col]; if (ok1) v1 += bias[col + 1]; }
                if (act & 1) {
                    v0 = 0.5f * v0 * (1.f + erff(v0 * 0.70710678118654752f));
                    v1 = 0.5f * v1 * (1.f + erff(v1 * 0.70710678118654752f));
                }
                long long off = coff + row * ldcr + (long long)col * ldcc;
                if (act & 2) {
                    __half* Ch = (__half*)C;
                    if (vec && ok1) *(__half2*)(Ch + off) = __halves2half2(__float2half(v0), __float2half(v1));
                    else {
                        Ch[off] = __float2half(v0);
                        if (ok1) Ch[off + ldcc] = __float2half(v1);
                    }
                } else {
                    if (vec && ok1) *(float2*)(C + off) = make_float2(v0, v1);
                    else {
                        C[off] = v0;
                        if (ok1) C[off + ldcc] = v1;
                    }
                }
            }
        }
    }
}

// ---------------- all weights f32 -> f16, QKV interleaved [l][3][D][D] ----------------
#define SEG0 ((long long)CD*CS)
#define SEG1 (SEG0 + (long long)2*DD)
#define SEG2 (SEG1 + (long long)2*DD)
#define SEG3 (SEG2 + (long long)2*DD)
#define SEG4 (SEG3 + (long long)2*DD)
#define SEG5 (SEG4 + (long long)2*CDF*CD)
#define SEG6 (SEG5 + (long long)2*CDF*CD)
#define SEG7 (SEG6 + (long long)CP*CD)
__global__ void f2h_all(const float* __restrict__ s0, const float* __restrict__ s1,
                        const float* __restrict__ s2, const float* __restrict__ s3,
                        const float* __restrict__ s4, const float* __restrict__ s5,
                        const float* __restrict__ s6, const float* __restrict__ s7,
                        __half* __restrict__ w)
{
    long long i = (long long)blockIdx.x * blockDim.x + threadIdx.x;
    if (i >= SEG7) return;
    float v; long long dst;
    if (i < SEG0) { v = s0[i]; dst = W_EMB + i; }
    else if (i < SEG1) { long long f = i - SEG0; long long l = f / (long long)DD, r = f % (long long)DD;
                         v = s1[f]; dst = W_QKV + l * 3 * DD + 0 * DD + r; }
    else if (i < SEG2) { long long f = i - SEG1; long long l = f / (long long)DD, r = f % (long long)DD;
                         v = s2[f]; dst = W_QKV + l * 3 * DD + 1 * DD + r; }
    else if (i < SEG3) { long long f = i - SEG2; long long l = f / (long long)DD, r = f % (long long)DD;
                         v = s3[f]; dst = W_QKV + l * 3 * DD + 2 * DD + r; }
    else if (i < SEG4) { v = s4[i - SEG3]; dst = W_WO + (i - SEG3); }
    else if (i < SEG5) { v = s5[i - SEG4]; dst = W_W1 + (i - SEG4); }
    else if (i < SEG6) { v = s6[i - SEG5]; dst = W_W2 + (i - SEG5); }
    else               { v = s7[i - SEG6]; dst = W_PW + (i - SEG6); }
    w[dst] = __float2half(v);
}

__global__ void bias_concat(const float* __restrict__ bq, const float* __restrict__ bk,
                            const float* __restrict__ bv, float* __restrict__ out)
{
    int i = blockIdx.x * blockDim.x + threadIdx.x;
    if (i >= 2 * 3 * CD) return;
    int l = i / (3 * CD), r = i % (3 * CD);
    const float* src = (r < CD) ? bq : ((r < 2 * CD) ? bk : bv);
    out[i] = src[l * CD + (r % CD)];
}

// ---------------- per-(b,n) stats over S ----------------
__global__ void stats_kernel(const float* __restrict__ x, float* __restrict__ mean,
                             float* __restrict__ stdv)
{
    int bn = blockIdx.x;
    int b = bn / CN, n = bn % CN;
    const float* p = x + (long long)b * CS * CN + n;
    float s = 0.f, s2 = 0.f;
    for (int i = threadIdx.x; i < CS; i += blockDim.x) {
        float v = p[(long long)i * CN];
        s += v; s2 += v * v;
    }
    __shared__ float rs[128], rq[128];
    rs[threadIdx.x] = s; rq[threadIdx.x] = s2; __syncthreads();
    for (int o = 64; o > 0; o >>= 1) {
        if (threadIdx.x < o) { rs[threadIdx.x] += rs[threadIdx.x + o]; rq[threadIdx.x] += rq[threadIdx.x + o]; }
        __syncthreads();
    }
    if (threadIdx.x == 0) {
        float mu = rs[0] / CS;
        float var = rq[0] / CS - mu * mu;
        mean[bn] = mu;
        stdv[bn] = sqrtf(var + 1e-5f);
    }
}

__global__ void norm_t_kernel(const float* __restrict__ x, const float* __restrict__ mean,
                              const float* __restrict__ stdv, __half* __restrict__ xt)
{
    long long idx = (long long)blockIdx.x * blockDim.x + threadIdx.x;
    if (idx >= (long long)BND) return;
    int s = (int)(idx & (CS - 1));
    long long bn = idx >> 9;
    int b = (int)(bn / CN), n = (int)(bn % CN);
    xt[idx] = __float2half((x[((long long)b * CS + s) * CN + n] - mean[bn]) / stdv[bn]);
}

// ---------------- SWT decomposition (fp32 in, fp16 out) ----------------
__global__ void swt_dec_kernel(const float* __restrict__ h,
                               const float* __restrict__ f0g, const float* __restrict__ f1g,
                               __half* __restrict__ coef)
{
    int bn = blockIdx.x; int n = bn % CN;
    __shared__ float a[CD], b[CD];
    const float* hp = h + (long long)bn * CD;
    for (int d = threadIdx.x; d < CD; d += blockDim.x) a[d] = hp[d];
    float l0[3], l1[3];
    #pragma unroll
    for (int t = 0; t < 3; t++) { l0[t] = f0g[n * 3 + t]; l1[t] = f1g[n * 3 + t]; }
    __syncthreads();
    __half* cf = coef + (long long)bn * 4 * CD;
    for (int d = threadIdx.x; d < CD; d += blockDim.x) {
        int im = (d - 1) & 511, ip = (d + 1) & 511;
        cf[3 * CD + d] = __float2half(l1[0] * a[im] + l1[1] * a[d] + l1[2] * a[ip]);
        b[d]           = l0[0] * a[im] + l0[1] * a[d] + l0[2] * a[ip];
    }
    __syncthreads();
    for (int d = threadIdx.x; d < CD; d += blockDim.x) {
        int i0 = (d - 1) & 511, i1 = (d + 1) & 511, i2 = (d + 3) & 511;
        cf[2 * CD + d] = __float2half(l1[0] * b[i0] + l1[1] * b[i1] + l1[2] * b[i2]);
        a[d]           = l0[0] * b[i0] + l0[1] * b[i1] + l0[2] * b[i2];
    }
    __syncthreads();
    for (int d = threadIdx.x; d < CD; d += blockDim.x) {
        int i0 = (d - 2) & 511, i1 = (d + 2) & 511, i2 = (d + 6) & 511;
        cf[1 * CD + d] = __float2half(l1[0] * a[i0] + l1[1] * a[i1] + l1[2] * a[i2]);
        cf[0 * CD + d] = __float2half(l0[0] * a[i0] + l0[1] * a[i1] + l0[2] * a[i2]);
    }
}

// ---------------- SWT reconstruction (fp32 in, fp16 out) ----------------
__global__ void swt_rec_kernel(const float* __restrict__ c,
                               const float* __restrict__ g0g, const float* __restrict__ g1g,
                               __half* __restrict__ out)
{
    int bn = blockIdx.x; int n = bn % CN;
    const float* cp = c + (long long)bn * 4 * CD;
    __shared__ float a[CD], b[CD], det[CD];
    float f0[3], f1[3];
    #pragma unroll
    for (int t = 0; t < 3; t++) { f0[t] = g0g[n * 3 + t]; f1[t] = g1g[n * 3 + t]; }
    for (int d = threadIdx.x; d < CD; d += blockDim.x) { a[d] = cp[d]; det[d] = cp[CD + d]; }
    __syncthreads();
    for (int d = threadIdx.x; d < CD; d += blockDim.x) {
        int i0 = (d - 6) & 511, i1 = (d - 2) & 511, i2 = (d + 2) & 511;
        b[d] = 0.5f * (f0[0] * a[i0] + f0[1] * a[i1] + f0[2] * a[i2]
                     + f1[0] * det[i0] + f1[1] * det[i1] + f1[2] * det[i2]);
    }
    __syncthreads();
    for (int d = threadIdx.x; d < CD; d += blockDim.x) det[d] = cp[2 * CD + d];
    __syncthreads();
    for (int d = threadIdx.x; d < CD; d += blockDim.x) {
        int i0 = (d - 3) & 511, i1 = (d - 1) & 511, i2 = (d + 1) & 511;
        a[d] = 0.5f * (f0[0] * b[i0] + f0[1] * b[i1] + f0[2] * b[i2]
                     + f1[0] * det[i0] + f1[1] * det[i1] + f1[2] * det[i2]);
    }
    __syncthreads();
    for (int d = threadIdx.x; d < CD; d += blockDim.x) det[d] = cp[3 * CD + d];
    __syncthreads();
    __half* op = out + (long long)bn * CD;
    for (int d = threadIdx.x; d < CD; d += blockDim.x) {
        int i0 = (d - 1) & 511, i2 = (d + 1) & 511;
        op[d] = __float2half(0.5f * (f0[0] * a[i0] + f0[1] * a[d] + f0[2] * a[i2]
                                   + f1[0] * det[i0] + f1[1] * det[d] + f1[2] * det[i2]));
    }
}

// ---------------- transpose fp16 [b][n][m][*ldin] -> [b][m][e][KPAD] ----------------
__global__ void trans_kernel(const __half* __restrict__ in, __half* __restrict__ out, int ldin)
{
    int z = blockIdx.z; int b = z >> 2, m = z & 3;
    __shared__ __half t[32][34];
    int e0 = blockIdx.x * 32, n0 = blockIdx.y * 32;
    int tx = threadIdx.x, ty = threadIdx.y;
    #pragma unroll
    for (int j = 0; j < 4; j++) {
        int e = e0 + tx, n = n0 + ty + j * 8;
        t[ty + j * 8][tx] = (n < CN) ? in[(long long)(((long long)b * CN + n) * 4 + m) * ldin + e]
                                     : __float2half(0.f);
    }
    __syncthreads();
    #pragma unroll
    for (int j = 0; j < 4; j++) {
        int n = n0 + tx, e = e0 + ty + j * 8;
        out[(((long long)b * 4 + m) * CD + e) * KPAD + n] = t[tx][ty + j * 8];
    }
}

// ---------------- row squared-norm: warp per row (padding is zero) ----------------
__global__ void rowsq_kernel(const __half* __restrict__ in, float* __restrict__ out)
{
    int row = blockIdx.x * 8 + (threadIdx.x >> 5);
    int lane = threadIdx.x & 31;
    const __half2* p = (const __half2*)(in + (long long)row * KPAD);
    float s = 0.f;
    #pragma unroll
    for (int i = lane; i < KPAD / 2; i += 32) {
        float2 v = __half22float2(p[i]);
        s += v.x * v.x + v.y * v.y;
    }
    #pragma unroll
    for (int o = 16; o > 0; o >>= 1) s += __shfl_xor_sync(0xFFFFFFFFu, s, o);
    if (lane == 0) out[row] = s;
}

// ---------------- wedge score + softmax (fp32 in, fp16 probs out) ----------------
__global__ void score_softmax_kernel(const float* __restrict__ dot,
                                     const float* __restrict__ qn2,
                                     const float* __restrict__ kn2,
                                     __half* __restrict__ prob)
{
    int row = blockIdx.x;
    int z = row >> 9;
    float q2 = qn2[row];
    const float* p = dot + (long long)row * CD;
    __half* pr = prob + (long long)row * CD;
    const float* k2 = kn2 + (long long)z * CD;
    const float scale = 1.f / sqrtf((float)CN);
    int t = threadIdx.x;
    float sc[2];
    float mx = -1e30f;
    #pragma unroll
    for (int j = 0; j < 2; j++) {
        int s = t + j * 256;
        float d = p[s];
        float w = sqrtf(fmaxf(q2 * k2[s] - d * d, 0.f) + 1e-8f);
        float v = ((1.f - ALPHA_) * d + ALPHA_ * w) * scale;
        sc[j] = v;
        mx = fmaxf(mx, v);
    }
    __shared__ float red[256];
    red[t] = mx; __syncthreads();
    for (int o = 128; o > 0; o >>= 1) {
        if (t < o) red[t] = fmaxf(red[t], red[t + o]);
        __syncthreads();
    }
    mx = red[0]; __syncthreads();
    float sum = 0.f;
    #pragma unroll
    for (int j = 0; j < 2; j++) { sc[j] = expf(sc[j] - mx); sum += sc[j]; }
    red[t] = sum; __syncthreads();
    for (int o = 128; o > 0; o >>= 1) {
        if (t < o) red[t] += red[t + o];
        __syncthreads();
    }
    float inv = 1.f / red[0];
    #pragma unroll
    for (int j = 0; j < 2; j++) pr[t + j * 256] = __float2half(sc[j] * inv);
}

// ---------------- add + layernorm ----------------
__global__ void add_ln_kernel(const float* __restrict__ x, const float* __restrict__ y,
                              const float* __restrict__ g, const float* __restrict__ bb,
                              float* __restrict__ out, __half* __restrict__ outh)
{
    int bn = blockIdx.x;
    const float* xp = x + (long long)bn * CD;
    const float* yp = y ? y + (long long)bn * CD : nullptr;
    int t = threadIdx.x;
    float v[2];
    float s = 0.f;
    #pragma unroll
    for (int j = 0; j < 2; j++) {
        int d = t + j * 256;
        v[j] = xp[d] + (yp ? yp[d] : 0.f);
        s += v[j];
    }
    __shared__ float red[256];
    red[t] = s; __syncthreads();
    for (int o = 128; o > 0; o >>= 1) { if (t < o) red[t] += red[t + o]; __syncthreads(); }
    float mu = red[0] / CD; __syncthreads();
    float s2 = 0.f;
    #pragma unroll
    for (int j = 0; j < 2; j++) { float dv = v[j] - mu; s2 += dv * dv; }
    red[t] = s2; __syncthreads();
    for (int o = 128; o > 0; o >>= 1) { if (t < o) red[t] += red[t + o]; __syncthreads(); }
    float inv = 1.f / sqrtf(red[0] / CD + 1e-5f);
    #pragma unroll
    for (int j = 0; j < 2; j++) {
        int d = t + j * 256;
        float r = (v[j] - mu) * inv * g[d] + bb[d];
        if (out)  out[(long long)bn * CD + d] = r;
        if (outh) outh[(long long)bn * CD + d] = __float2half(r);
    }
}

// ---------------- final output de-normalization ----------------
__global__ void out_kernel(const float* __restrict__ dec, const float* __restrict__ mean,
                           const float* __restrict__ stdv, float* __restrict__ out)
{
    int idx = blockIdx.x * blockDim.x + threadIdx.x;
    if (idx >= CB * CP * CN) return;
    int n = idx % CN;
    int p = (idx / CN) % CP;
    int b = idx / (CN * CP);
    int bn = b * CN + n;
    out[idx] = dec[(long long)bn * CP + p] * stdv[bn] + mean[bn];
}

__global__ void aux_out_kernel(const float* __restrict__ mean, const float* __restrict__ stdv,
                               float* __restrict__ out)
{
    int i = blockIdx.x * blockDim.x + threadIdx.x;
    if (i >= CBN) return;
    out[CB * CP * CN + i] = mean[i];
    out[CB * CP * CN + CBN + i] = stdv[i];
}

// ---------------- host orchestration ----------------
static void launch_tc(const __half* A, const __half* B, float* C, const float* bias,
                      int M, int Nn, int Kd, int lda, int ldb,
                      long long ldcr, long long ldcc,
                      int batches, int bdiv,
                      long long sAh, long long sAl,
                      long long sBh, long long sBl,
                      long long sCh, long long sCl, int act)
{
    long long b128 = (long long)((M + 127) / 128) * ((Nn + 127) / 128) * batches;
    if (b128 >= 296) {
        dim3 grid((M + 127) / 128, (Nn + 127) / 128, batches);
        gemm_tc<128, 4, 3><<<grid, 128, SMEM_128>>>(A, B, C, bias, M, Nn, Kd, lda, ldb,
            ldcr, ldcc, bdiv, sAh, sAl, sBh, sBl, sCh, sCl, act);
    } else {
        dim3 grid((M + 63) / 64, (Nn + 127) / 128, batches);
        gemm_tc<64, 2, 2><<<grid, 128, SMEM_64>>>(A, B, C, bias, M, Nn, Kd, lda, ldb,
            ldcr, ldcc, bdiv, sAh, sAl, sBh, sBl, sCh, sCl, act);
    }
}

extern "C" void kernel_launch(void* const* d_in, const int* in_sizes, int n_in,
                              void* d_out, int out_size)
{
    (void)in_sizes; (void)n_in;
    const float* x_enc  = (const float*)d_in[0];
    const float* emb_W  = (const float*)d_in[1];
    const float* emb_b  = (const float*)d_in[2];
    const float* h0     = (const float*)d_in[3];
    const float* h1     = (const float*)d_in[4];
    const float* g0     = (const float*)d_in[5];
    const float* g1     = (const float*)d_in[6];
    const float* Wq     = (const float*)d_in[7];
    const float* bq     = (const float*)d_in[8];
    const float* Wk     = (const float*)d_in[9];
    const float* bk     = (const float*)d_in[10];
    const float* Wv     = (const float*)d_in[11];
    const float* bv     = (const float*)d_in[12];
    const float* Wo     = (const float*)d_in[13];
    const float* bo     = (const float*)d_in[14];
    const float* W1     = (const float*)d_in[15];
    const float* b1     = (const float*)d_in[16];
    const float* W2     = (const float*)d_in[17];
    const float* b2     = (const float*)d_in[18];
    const float* ln1_g  = (const float*)d_in[19];
    const float* ln1_b  = (const float*)d_in[20];
    const float* ln2_g  = (const float*)d_in[21];
    const float* ln2_b  = (const float*)d_in[22];
    const float* lnf_g  = (const float*)d_in[23];
    const float* lnf_b  = (const float*)d_in[24];
    const float* proj_W = (const float*)d_in[25];
    const float* proj_b = (const float*)d_in[26];

    cudaFuncSetAttribute(gemm_tc<128, 4, 3>, cudaFuncAttributeMaxDynamicSharedMemorySize, SMEM_128);
    cudaFuncSetAttribute(gemm_tc<64, 2, 2>,  cudaFuncAttributeMaxDynamicSharedMemorySize, SMEM_64);

    float* ws = nullptr;
    cudaGetSymbolAddress((void**)&ws, g_ws);
    __half* hw = nullptr;
    cudaGetSymbolAddress((void**)&hw, g_hws);

    float* h    = ws + O_H;
    float* mean = ws + O_MEAN;
    float* stdv = ws + O_STD;
    float* bqkv = ws + O_BQKV;
    float* dot  = ws + O_DOT;
    float* ao   = ws + O_AO;
    float* att  = ws + O_ATT;
    float* x1   = ws + O_X1;
    float* y2   = ws + O_Y2;
    float* dec  = ws + O_DEC;

    __half* xt_h  = hw + H_XT;
    __half* coefh = hw + H_COEF;
    __half* qkv   = hw + H_QKV;
    __half* qah   = hw + H_QA;
    __half* kah   = hw + H_KA;
    __half* prob  = hw + H_PROB;
    __half* rech  = hw + H_REC;
    __half* x1h   = hw + H_X1;
    __half* ffh   = hw + H_FF;
    __half* wts   = hw + H_WTS;
    __half* embWh = wts + W_EMB;
    __half* qkvWh = wts + W_QKV;
    __half* Woh   = wts + W_WO;
    __half* W1h   = wts + W_W1;
    __half* W2h   = wts + W_W2;
    __half* pWh   = wts + W_PW;

    // qn2/kn2 borrow the front of ao: softmax consumes them before AV writes ao
    float* qn2b = ao;
    float* kn2b = ao + (size_t)CB * 4 * CD;

    f2h_all<<<(int)((SEG7 + 255) / 256), 256>>>(emb_W, Wq, Wk, Wv, Wo, W1, W2, proj_W, wts);
    bias_concat<<<(2 * 3 * CD + 255) / 256, 256>>>(bq, bk, bv, bqkv);

    stats_kernel<<<CBN, 128>>>(x_enc, mean, stdv);
    norm_t_kernel<<<(int)((BND + 255) / 256), 256>>>(x_enc, mean, stdv, xt_h);

    launch_tc(xt_h, embWh, h, emb_b, CBN, CD, CS, CS, CS, CD, 1,
              1, 1, 0, 0, 0, 0, 0, 0, 0);

    const long long ZAP = (long long)CD * KPAD;
    const long long ZD  = (long long)CD * CD;
    const long long BSTR = (long long)CN * 4 * CD;
    const long long QSTR = (long long)CN * 4 * 1536;

    for (int l = 0; l < 2; l++) {
        swt_dec_kernel<<<CBN, 256>>>(h, h0 + (long long)l * CN * 3, h1 + (long long)l * CN * 3, coefh);

        // fused QKV: one GEMM, N = 1536, fp16 out into qkv[b][n][m][1536]
        launch_tc(coefh, qkvWh + (long long)l * 3 * DD, (float*)qkv, bqkv + (long long)l * 3 * CD,
                  CBN * 4, 3 * CD, CD, CD, CD, 3 * CD, 1, 1, 1, 0, 0, 0, 0, 0, 0, 2);

        {
            dim3 g2(16, KPAD / 32, CB * 4), b2d(32, 8);
            trans_kernel<<<g2, b2d>>>(qkv,       qah, 1536);
            trans_kernel<<<g2, b2d>>>(qkv + 512, kah, 1536);
        }
        rowsq_kernel<<<CB * 4 * CD / 8, 256>>>(qah, qn2b);
        rowsq_kernel<<<CB * 4 * CD / 8, 256>>>(kah, kn2b);

        launch_tc(qah, kah, dot, nullptr, CD, CD, KPAD, KPAD, KPAD, CD, 1,
                  CB * 4, 1, ZAP, 0, ZAP, 0, ZD, 0, 0);

        score_softmax_kernel<<<CB * 4 * CD, 256>>>(dot, qn2b, kn2b, prob);

        // AV with V sliced from qkv (cols 1024..1535), scatter into coeffs layout
        launch_tc(prob, qkv + 1024, ao, nullptr, CD, CN, CD, CD, 4 * 1536, 1, 4 * CD,
                  CB * 4, 4,
                  4 * ZD, ZD,
                  QSTR, 1536,
                  BSTR, CD,
                  0);

        swt_rec_kernel<<<CBN, 256>>>(ao, g0 + (long long)l * CN * 3, g1 + (long long)l * CN * 3, rech);

        launch_tc(rech, Woh + (long long)l * DD, att, bo + (long long)l * CD,
                  CBN, CD, CD, CD, CD, CD, 1, 1, 1, 0, 0, 0, 0, 0, 0, 0);

        add_ln_kernel<<<CBN, 256>>>(h, att, ln1_g + (long long)l * CD, ln1_b + (long long)l * CD, x1, x1h);

        launch_tc(x1h, W1h + (long long)l * CDF * CD, (float*)ffh, b1 + (long long)l * CDF,
                  CBN, CDF, CD, CD, CD, CDF, 1, 1, 1, 0, 0, 0, 0, 0, 0, 3);
        launch_tc(ffh, W2h + (long long)l * CD * CDF, y2, b2 + (long long)l * CD,
                  CBN, CD, CDF, CDF, CDF, CD, 1, 1, 1, 0, 0, 0, 0, 0, 0, 0);

        add_ln_kernel<<<CBN, 256>>>(x1, y2, ln2_g + (long long)l * CD, ln2_b + (long long)l * CD, h, nullptr);
    }

    add_ln_kernel<<<CBN, 256>>>(h, nullptr, lnf_g, lnf_b, nullptr, x1h);
    launch_tc(x1h, pWh, dec, proj_b, CBN, CP, CD, CD, CD, CP, 1,
              1, 1, 0, 0, 0, 0, 0, 0, 0);

    out_kernel<<<(CB * CP * CN + 255) / 256, 256>>>(dec, mean, stdv, (float*)d_out);
    if (out_size >= CB * CP * CN + 2 * CBN) {
        aux_out_kernel<<<(CBN + 255) / 256, 256>>>(mean, stdv, (float*)d_out);
    }
}

// round 16
// speedup vs baseline: 1.1203x; 1.1203x over previous
#include <cuda_runtime.h>
#include <cuda_fp16.h>
#include <math.h>
#include <stdint.h>

#define CB 16
#define CS 512
#define CN 321
#define CD 512
#define CDF 2048
#define CP 96
#define KPAD 384
#define CBN (CB*CN)
#define DD ((size_t)CD*CD)
#define BND ((size_t)CBN*CD)
#define BNMD ((size_t)CBN*4*CD)
#define QAPAD ((size_t)CB*4*CD*KPAD)
#define ATT ((size_t)CB*4*CD*CD)
#define ALPHA_ 0.3f

// ---------------- fp32 workspace ----------------
#define O_H    ((size_t)0)
#define O_MEAN (O_H + BND)
#define O_STD  (O_MEAN + CBN)
#define O_BQKV (O_STD + CBN)          /* 2*3*CD */
#define O_DOT  (O_BQKV + 2*3*CD)
#define O_AO   (O_DOT + ATT)
#define O_ATT  (O_AO + BNMD)
#define O_X1   (O_ATT + BND)
#define O_Y2   (O_X1 + BND)
#define O_DEC  (O_Y2 + BND)
#define WS_TOTAL (O_DEC + (size_t)CBN*CP)
__device__ float g_ws[WS_TOTAL];

// ---------------- fp16 workspace ----------------
#define H_XT   ((size_t)0)
#define H_COEF (H_XT + BND)
#define H_QKV  (H_COEF + BNMD)              /* [b][n][m][1536] */
#define H_QA   (H_QKV + (size_t)CBN*4*1536)
#define H_KA   (H_QA + QAPAD)
#define H_PROB (H_KA + QAPAD)
#define H_REC  (H_PROB + ATT)
#define H_X1   (H_REC + BND)
#define H_FF   (H_X1 + BND)
#define H_WTS  (H_FF + (size_t)CBN*CDF)
/* weight sub-offsets inside H_WTS */
#define W_EMB  ((size_t)0)
#define W_QKV  (W_EMB + (size_t)CD*CS)      /* [l][3][D][D] */
#define W_WO   (W_QKV + 6*DD)
#define W_W1   (W_WO + 2*DD)
#define W_W2   (W_W1 + (size_t)2*CDF*CD)
#define W_PW   (W_W2 + (size_t)2*CDF*CD)
#define W_TOTAL (W_PW + (size_t)CP*CD)
#define HW_TOTAL (H_WTS + W_TOTAL)
__device__ __align__(16) __half g_hws[HW_TOTAL];

// ---------------- helpers ----------------
__device__ __forceinline__ uint32_t smem_u32(const void* p) {
    uint32_t a;
    asm("{ .reg .u64 t; cvta.to.shared.u64 t, %1; cvt.u32.u64 %0, t; }" : "=r"(a) : "l"(p));
    return a;
}
__device__ __forceinline__ void cp16(uint32_t dst, const void* src, int sz) {
    asm volatile("cp.async.cg.shared.global [%0], [%1], 16, %2;"
                 :: "r"(dst), "l"(src), "r"(sz));
}
__device__ __forceinline__ void cp_commit() { asm volatile("cp.async.commit_group;" ::: "memory"); }

#define ASTRIDE 72                    /* halves; 144B pitch -> LDSM conflict-free */

// async load ROWS x 64 halves of a K-chunk, zero-pad rows >= rows
template<int ROWS, int NT>
__device__ __forceinline__ void load_chunk(const __half* __restrict__ g, int rows, int ld,
                                           int k0, uint32_t smbase, int tid) {
    #pragma unroll
    for (int i = 0; i < ROWS * 8 / NT; i++) {
        int idx = tid + i * NT;
        int r = idx >> 3, c = idx & 7;
        int ok = r < rows;
        const __half* src = g + (long long)(ok ? r : 0) * ld + k0 + c * 8;
        cp16(smbase + (uint32_t)(r * ASTRIDE + c * 8) * 2u, src, ok ? 16 : 0);
    }
}

#define SMEM_128 (3*(128+128)*ASTRIDE*2)   /* 110592 */
#define SMEM_64  (2*( 64+128)*ASTRIDE*2)   /* 55296  */

// ============ generic batched NT GEMM via mma.sync fp16 + ldmatrix ============
// C[row,col] = sum_k A[row,k]*B[col,k] (+bias[col])
// act bit0 = gelu, bit1 = fp16 output (C as __half*)
// BM in {64,128}; BN=128; NT = BM*2 threads; warp tile 32x64.
template<int BM, int NT, int NSTAGE>
__global__ __launch_bounds__(NT, (BM == 128) ? 2 : 4) void gemm_tc(
    const __half* __restrict__ A, const __half* __restrict__ Bm,
    float* __restrict__ C, const float* __restrict__ bias,
    int M, int Nn, int Kd, int lda, int ldb,
    long long ldcr, long long ldcc, int bdiv,
    long long sAh, long long sAl, long long sBh, long long sBl,
    long long sCh, long long sCl, int act)
{
    constexpr int WR = BM / 32;                       // warp rows
    constexpr int STAGE_B = (BM + 128) * ASTRIDE * 2; // bytes per stage
    extern __shared__ __half smh[];
    const int tid = threadIdx.x;
    const int wid = tid >> 5, lane = tid & 31;
    const int gid = lane >> 2, tig = lane & 3;
    const int wr = wid % WR, wc = wid / WR;

    int z = blockIdx.z;
    int zh = z / bdiv, zl = z % bdiv;
    A  += zh * sAh + zl * sAl;
    Bm += zh * sBh + zl * sBl;
    long long coff = zh * sCh + zl * sCl;

    int m0 = blockIdx.x * BM, n0 = blockIdx.y * 128;
    int mrem = M - m0, nrem = Nn - n0;
    const __half* Ag = A + (long long)m0 * lda;
    const __half* Bg = Bm + (long long)n0 * ldb;

    uint32_t smb = smem_u32(smh);

    // ldmatrix per-lane row offsets (halves)
    const int aRow = (wr * 32 + (lane & 15)) * ASTRIDE + (lane >> 4) * 8;
    const int mID = lane >> 3, rID = lane & 7;
    const int bRow = (((mID >> 1) << 3) + rID) * ASTRIDE + (mID & 1) * 8;
    const int bColBase = wc * 64;

    float c[2][8][4];
    #pragma unroll
    for (int i = 0; i < 2; i++)
        #pragma unroll
        for (int j = 0; j < 8; j++)
            #pragma unroll
            for (int r = 0; r < 4; r++) c[i][j][r] = 0.f;

    const int NC = Kd >> 6;   // K chunks of 64

    #pragma unroll
    for (int s = 0; s < NSTAGE - 1; s++) {
        if (s < NC) {
            load_chunk<BM, NT>(Ag, mrem, lda, s << 6, smb + s * STAGE_B, tid);
            load_chunk<128, NT>(Bg, nrem, ldb, s << 6, smb + s * STAGE_B + BM * ASTRIDE * 2, tid);
        }
        cp_commit();
    }

    for (int ch = 0; ch < NC; ch++) {
        asm volatile("cp.async.wait_group %0;" :: "n"(NSTAGE - 2));
        __syncthreads();
        int pf = ch + NSTAGE - 1;
        if (pf < NC) {
            int s = pf % NSTAGE;
            load_chunk<BM, NT>(Ag, mrem, lda, pf << 6, smb + s * STAGE_B, tid);
            load_chunk<128, NT>(Bg, nrem, ldb, pf << 6, smb + s * STAGE_B + BM * ASTRIDE * 2, tid);
        }
        cp_commit();

        int cs = ch % NSTAGE;
        uint32_t aB = smb + cs * STAGE_B;
        uint32_t bB = aB + BM * ASTRIDE * 2 + (uint32_t)(bColBase * ASTRIDE) * 2u;

        #pragma unroll
        for (int ks = 0; ks < 4; ks++) {
            int kc = ks << 4;
            uint32_t a[2][4], b[8][2];
            #pragma unroll
            for (int i = 0; i < 2; i++) {
                uint32_t ad = aB + (uint32_t)(aRow + i * 16 * ASTRIDE + kc) * 2u;
                asm volatile("ldmatrix.sync.aligned.m8n8.x4.shared.b16 {%0,%1,%2,%3}, [%4];"
                    : "=r"(a[i][0]), "=r"(a[i][1]), "=r"(a[i][2]), "=r"(a[i][3]) : "r"(ad));
            }
            #pragma unroll
            for (int jp = 0; jp < 4; jp++) {
                uint32_t bd = bB + (uint32_t)(bRow + jp * 16 * ASTRIDE + kc) * 2u;
                asm volatile("ldmatrix.sync.aligned.m8n8.x4.shared.b16 {%0,%1,%2,%3}, [%4];"
                    : "=r"(b[2*jp][0]), "=r"(b[2*jp][1]),
                      "=r"(b[2*jp+1][0]), "=r"(b[2*jp+1][1]) : "r"(bd));
            }
            #pragma unroll
            for (int i = 0; i < 2; i++)
                #pragma unroll
                for (int j = 0; j < 8; j++) {
                    asm volatile(
                        "mma.sync.aligned.m16n8k16.row.col.f32.f16.f16.f32 "
                        "{%0,%1,%2,%3}, {%4,%5,%6,%7}, {%8,%9}, {%0,%1,%2,%3};"
                        : "+f"(c[i][j][0]), "+f"(c[i][j][1]),
                          "+f"(c[i][j][2]), "+f"(c[i][j][3])
                        : "r"(a[i][0]), "r"(a[i][1]), "r"(a[i][2]), "r"(a[i][3]),
                          "r"(b[j][0]), "r"(b[j][1]));
                }
        }
    }

    // epilogue
    const bool vec = (ldcc == 1);
    #pragma unroll
    for (int i = 0; i < 2; i++) {
        int rbase = wr * 32 + i * 16 + gid;
        #pragma unroll
        for (int half = 0; half < 2; half++) {
            int rloc = rbase + half * 8;
            if (rloc >= mrem) continue;
            long long row = m0 + rloc;
            #pragma unroll
            for (int j = 0; j < 8; j++) {
                int cloc = bColBase + j * 8 + tig * 2;
                bool ok0 = cloc < nrem, ok1 = cloc + 1 < nrem;
                if (!ok0) continue;
                int col = n0 + cloc;
                float v0 = c[i][j][half * 2], v1 = c[i][j][half * 2 + 1];
                if (bias) { v0 += bias[col]; if (ok1) v1 += bias[col + 1]; }
                if (act & 1) {
                    v0 = 0.5f * v0 * (1.f + erff(v0 * 0.70710678118654752f));
                    v1 = 0.5f * v1 * (1.f + erff(v1 * 0.70710678118654752f));
                }
                long long off = coff + row * ldcr + (long long)col * ldcc;
                if (act & 2) {
                    __half* Ch = (__half*)C;
                    if (vec && ok1) *(__half2*)(Ch + off) = __halves2half2(__float2half(v0), __float2half(v1));
                    else {
                        Ch[off] = __float2half(v0);
                        if (ok1) Ch[off + ldcc] = __float2half(v1);
                    }
                } else {
                    if (vec && ok1) *(float2*)(C + off) = make_float2(v0, v1);
                    else {
                        C[off] = v0;
                        if (ok1) C[off + ldcc] = v1;
                    }
                }
            }
        }
    }
}

// ---------------- all weights f32 -> f16, QKV interleaved [l][3][D][D] ----------------
#define SEG0 ((long long)CD*CS)
#define SEG1 (SEG0 + (long long)2*DD)
#define SEG2 (SEG1 + (long long)2*DD)
#define SEG3 (SEG2 + (long long)2*DD)
#define SEG4 (SEG3 + (long long)2*DD)
#define SEG5 (SEG4 + (long long)2*CDF*CD)
#define SEG6 (SEG5 + (long long)2*CDF*CD)
#define SEG7 (SEG6 + (long long)CP*CD)
__global__ void f2h_all(const float* __restrict__ s0, const float* __restrict__ s1,
                        const float* __restrict__ s2, const float* __restrict__ s3,
                        const float* __restrict__ s4, const float* __restrict__ s5,
                        const float* __restrict__ s6, const float* __restrict__ s7,
                        __half* __restrict__ w)
{
    long long i = (long long)blockIdx.x * blockDim.x + threadIdx.x;
    if (i >= SEG7) return;
    float v; long long dst;
    if (i < SEG0) { v = s0[i]; dst = W_EMB + i; }
    else if (i < SEG1) { long long f = i - SEG0; long long l = f / (long long)DD, r = f % (long long)DD;
                         v = s1[f]; dst = W_QKV + l * 3 * DD + 0 * DD + r; }
    else if (i < SEG2) { long long f = i - SEG1; long long l = f / (long long)DD, r = f % (long long)DD;
                         v = s2[f]; dst = W_QKV + l * 3 * DD + 1 * DD + r; }
    else if (i < SEG3) { long long f = i - SEG2; long long l = f / (long long)DD, r = f % (long long)DD;
                         v = s3[f]; dst = W_QKV + l * 3 * DD + 2 * DD + r; }
    else if (i < SEG4) { v = s4[i - SEG3]; dst = W_WO + (i - SEG3); }
    else if (i < SEG5) { v = s5[i - SEG4]; dst = W_W1 + (i - SEG4); }
    else if (i < SEG6) { v = s6[i - SEG5]; dst = W_W2 + (i - SEG5); }
    else               { v = s7[i - SEG6]; dst = W_PW + (i - SEG6); }
    w[dst] = __float2half(v);
}

__global__ void bias_concat(const float* __restrict__ bq, const float* __restrict__ bk,
                            const float* __restrict__ bv, float* __restrict__ out)
{
    int i = blockIdx.x * blockDim.x + threadIdx.x;
    if (i >= 2 * 3 * CD) return;
    int l = i / (3 * CD), r = i % (3 * CD);
    const float* src = (r < CD) ? bq : ((r < 2 * CD) ? bk : bv);
    out[i] = src[l * CD + (r % CD)];
}

// ---------------- per-(b,n) stats over S ----------------
__global__ void stats_kernel(const float* __restrict__ x, float* __restrict__ mean,
                             float* __restrict__ stdv)
{
    int bn = blockIdx.x;
    int b = bn / CN, n = bn % CN;
    const float* p = x + (long long)b * CS * CN + n;
    float s = 0.f, s2 = 0.f;
    for (int i = threadIdx.x; i < CS; i += blockDim.x) {
        float v = p[(long long)i * CN];
        s += v; s2 += v * v;
    }
    __shared__ float rs[128], rq[128];
    rs[threadIdx.x] = s; rq[threadIdx.x] = s2; __syncthreads();
    for (int o = 64; o > 0; o >>= 1) {
        if (threadIdx.x < o) { rs[threadIdx.x] += rs[threadIdx.x + o]; rq[threadIdx.x] += rq[threadIdx.x + o]; }
        __syncthreads();
    }
    if (threadIdx.x == 0) {
        float mu = rs[0] / CS;
        float var = rq[0] / CS - mu * mu;
        mean[bn] = mu;
        stdv[bn] = sqrtf(var + 1e-5f);
    }
}

// ---------------- tiled normalize-transpose: xt[bn][s] = (x[b,s,n]-mu)/sd ----------------
__global__ void norm_t_kernel(const float* __restrict__ x, const float* __restrict__ mean,
                              const float* __restrict__ stdv, __half* __restrict__ xt)
{
    __shared__ float t[32][33];
    int b = blockIdx.z;
    int n0 = blockIdx.x * 32, s0 = blockIdx.y * 32;
    int tx = threadIdx.x, ty = threadIdx.y;
    #pragma unroll
    for (int j = 0; j < 4; j++) {
        int s = s0 + ty + j * 8, n = n0 + tx;
        if (n < CN) t[ty + j * 8][tx] = x[((long long)b * CS + s) * CN + n];
    }
    __syncthreads();
    #pragma unroll
    for (int j = 0; j < 4; j++) {
        int n = n0 + ty + j * 8, s = s0 + tx;
        if (n < CN) {
            int bn = b * CN + n;
            xt[(long long)bn * CS + s] = __float2half((t[tx][ty + j * 8] - mean[bn]) / stdv[bn]);
        }
    }
}

// ---------------- SWT decomposition (fp32 in, fp16 out) ----------------
__global__ void swt_dec_kernel(const float* __restrict__ h,
                               const float* __restrict__ f0g, const float* __restrict__ f1g,
                               __half* __restrict__ coef)
{
    int bn = blockIdx.x; int n = bn % CN;
    __shared__ float a[CD], b[CD];
    const float* hp = h + (long long)bn * CD;
    for (int d = threadIdx.x; d < CD; d += blockDim.x) a[d] = hp[d];
    float l0[3], l1[3];
    #pragma unroll
    for (int t = 0; t < 3; t++) { l0[t] = f0g[n * 3 + t]; l1[t] = f1g[n * 3 + t]; }
    __syncthreads();
    __half* cf = coef + (long long)bn * 4 * CD;
    for (int d = threadIdx.x; d < CD; d += blockDim.x) {
        int im = (d - 1) & 511, ip = (d + 1) & 511;
        cf[3 * CD + d] = __float2half(l1[0] * a[im] + l1[1] * a[d] + l1[2] * a[ip]);
        b[d]           = l0[0] * a[im] + l0[1] * a[d] + l0[2] * a[ip];
    }
    __syncthreads();
    for (int d = threadIdx.x; d < CD; d += blockDim.x) {
        int i0 = (d - 1) & 511, i1 = (d + 1) & 511, i2 = (d + 3) & 511;
        cf[2 * CD + d] = __float2half(l1[0] * b[i0] + l1[1] * b[i1] + l1[2] * b[i2]);
        a[d]           = l0[0] * b[i0] + l0[1] * b[i1] + l0[2] * b[i2];
    }
    __syncthreads();
    for (int d = threadIdx.x; d < CD; d += blockDim.x) {
        int i0 = (d - 2) & 511, i1 = (d + 2) & 511, i2 = (d + 6) & 511;
        cf[1 * CD + d] = __float2half(l1[0] * a[i0] + l1[1] * a[i1] + l1[2] * a[i2]);
        cf[0 * CD + d] = __float2half(l0[0] * a[i0] + l0[1] * a[i1] + l0[2] * a[i2]);
    }
}

// ---------------- SWT reconstruction (fp32 in, fp16 out) ----------------
__global__ void swt_rec_kernel(const float* __restrict__ c,
                               const float* __restrict__ g0g, const float* __restrict__ g1g,
                               __half* __restrict__ out)
{
    int bn = blockIdx.x; int n = bn % CN;
    const float* cp = c + (long long)bn * 4 * CD;
    __shared__ float a[CD], b[CD], det[CD];
    float f0[3], f1[3];
    #pragma unroll
    for (int t = 0; t < 3; t++) { f0[t] = g0g[n * 3 + t]; f1[t] = g1g[n * 3 + t]; }
    for (int d = threadIdx.x; d < CD; d += blockDim.x) { a[d] = cp[d]; det[d] = cp[CD + d]; }
    __syncthreads();
    for (int d = threadIdx.x; d < CD; d += blockDim.x) {
        int i0 = (d - 6) & 511, i1 = (d - 2) & 511, i2 = (d + 2) & 511;
        b[d] = 0.5f * (f0[0] * a[i0] + f0[1] * a[i1] + f0[2] * a[i2]
                     + f1[0] * det[i0] + f1[1] * det[i1] + f1[2] * det[i2]);
    }
    __syncthreads();
    for (int d = threadIdx.x; d < CD; d += blockDim.x) det[d] = cp[2 * CD + d];
    __syncthreads();
    for (int d = threadIdx.x; d < CD; d += blockDim.x) {
        int i0 = (d - 3) & 511, i1 = (d - 1) & 511, i2 = (d + 1) & 511;
        a[d] = 0.5f * (f0[0] * b[i0] + f0[1] * b[i1] + f0[2] * b[i2]
                     + f1[0] * det[i0] + f1[1] * det[i1] + f1[2] * det[i2]);
    }
    __syncthreads();
    for (int d = threadIdx.x; d < CD; d += blockDim.x) det[d] = cp[3 * CD + d];
    __syncthreads();
    __half* op = out + (long long)bn * CD;
    for (int d = threadIdx.x; d < CD; d += blockDim.x) {
        int i0 = (d - 1) & 511, i2 = (d + 1) & 511;
        op[d] = __float2half(0.5f * (f0[0] * a[i0] + f0[1] * a[d] + f0[2] * a[i2]
                                   + f1[0] * det[i0] + f1[1] * det[d] + f1[2] * det[i2]));
    }
}

// ---------------- transpose fp16 [b][n][m][*ldin] -> [b][m][e][KPAD] ----------------
__global__ void trans_kernel(const __half* __restrict__ in, __half* __restrict__ out, int ldin)
{
    int z = blockIdx.z; int b = z >> 2, m = z & 3;
    __shared__ __half t[32][34];
    int e0 = blockIdx.x * 32, n0 = blockIdx.y * 32;
    int tx = threadIdx.x, ty = threadIdx.y;
    #pragma unroll
    for (int j = 0; j < 4; j++) {
        int e = e0 + tx, n = n0 + ty + j * 8;
        t[ty + j * 8][tx] = (n < CN) ? in[(long long)(((long long)b * CN + n) * 4 + m) * ldin + e]
                                     : __float2half(0.f);
    }
    __syncthreads();
    #pragma unroll
    for (int j = 0; j < 4; j++) {
        int n = n0 + tx, e = e0 + ty + j * 8;
        out[(((long long)b * 4 + m) * CD + e) * KPAD + n] = t[tx][ty + j * 8];
    }
}

// ---------------- row squared-norm: warp per row (padding is zero) ----------------
__global__ void rowsq_kernel(const __half* __restrict__ in, float* __restrict__ out)
{
    int row = blockIdx.x * 8 + (threadIdx.x >> 5);
    int lane = threadIdx.x & 31;
    const __half2* p = (const __half2*)(in + (long long)row * KPAD);
    float s = 0.f;
    #pragma unroll
    for (int i = lane; i < KPAD / 2; i += 32) {
        float2 v = __half22float2(p[i]);
        s += v.x * v.x + v.y * v.y;
    }
    #pragma unroll
    for (int o = 16; o > 0; o >>= 1) s += __shfl_xor_sync(0xFFFFFFFFu, s, o);
    if (lane == 0) out[row] = s;
}

// ---------------- wedge score + softmax (fp32 in, fp16 probs out) ----------------
__global__ void score_softmax_kernel(const float* __restrict__ dot,
                                     const float* __restrict__ qn2,
                                     const float* __restrict__ kn2,
                                     __half* __restrict__ prob)
{
    int row = blockIdx.x;
    int z = row >> 9;
    float q2 = qn2[row];
    const float* p = dot + (long long)row * CD;
    __half* pr = prob + (long long)row * CD;
    const float* k2 = kn2 + (long long)z * CD;
    const float scale = 1.f / sqrtf((float)CN);
    int t = threadIdx.x;
    float sc[2];
    float mx = -1e30f;
    #pragma unroll
    for (int j = 0; j < 2; j++) {
        int s = t + j * 256;
        float d = p[s];
        float w = sqrtf(fmaxf(q2 * k2[s] - d * d, 0.f) + 1e-8f);
        float v = ((1.f - ALPHA_) * d + ALPHA_ * w) * scale;
        sc[j] = v;
        mx = fmaxf(mx, v);
    }
    __shared__ float red[256];
    red[t] = mx; __syncthreads();
    for (int o = 128; o > 0; o >>= 1) {
        if (t < o) red[t] = fmaxf(red[t], red[t + o]);
        __syncthreads();
    }
    mx = red[0]; __syncthreads();
    float sum = 0.f;
    #pragma unroll
    for (int j = 0; j < 2; j++) { sc[j] = expf(sc[j] - mx); sum += sc[j]; }
    red[t] = sum; __syncthreads();
    for (int o = 128; o > 0; o >>= 1) {
        if (t < o) red[t] += red[t + o];
        __syncthreads();
    }
    float inv = 1.f / red[0];
    #pragma unroll
    for (int j = 0; j < 2; j++) pr[t + j * 256] = __float2half(sc[j] * inv);
}

// ---------------- add + layernorm ----------------
__global__ void add_ln_kernel(const float* __restrict__ x, const float* __restrict__ y,
                              const float* __restrict__ g, const float* __restrict__ bb,
                              float* __restrict__ out, __half* __restrict__ outh)
{
    int bn = blockIdx.x;
    const float* xp = x + (long long)bn * CD;
    const float* yp = y ? y + (long long)bn * CD : nullptr;
    int t = threadIdx.x;
    float v[2];
    float s = 0.f;
    #pragma unroll
    for (int j = 0; j < 2; j++) {
        int d = t + j * 256;
        v[j] = xp[d] + (yp ? yp[d] : 0.f);
        s += v[j];
    }
    __shared__ float red[256];
    red[t] = s; __syncthreads();
    for (int o = 128; o > 0; o >>= 1) { if (t < o) red[t] += red[t + o]; __syncthreads(); }
    float mu = red[0] / CD; __syncthreads();
    float s2 = 0.f;
    #pragma unroll
    for (int j = 0; j < 2; j++) { float dv = v[j] - mu; s2 += dv * dv; }
    red[t] = s2; __syncthreads();
    for (int o = 128; o > 0; o >>= 1) { if (t < o) red[t] += red[t + o]; __syncthreads(); }
    float inv = 1.f / sqrtf(red[0] / CD + 1e-5f);
    #pragma unroll
    for (int j = 0; j < 2; j++) {
        int d = t + j * 256;
        float r = (v[j] - mu) * inv * g[d] + bb[d];
        if (out)  out[(long long)bn * CD + d] = r;
        if (outh) outh[(long long)bn * CD + d] = __float2half(r);
    }
}

// ---------------- final output de-normalization ----------------
__global__ void out_kernel(const float* __restrict__ dec, const float* __restrict__ mean,
                           const float* __restrict__ stdv, float* __restrict__ out)
{
    int idx = blockIdx.x * blockDim.x + threadIdx.x;
    if (idx >= CB * CP * CN) return;
    int n = idx % CN;
    int p = (idx / CN) % CP;
    int b = idx / (CN * CP);
    int bn = b * CN + n;
    out[idx] = dec[(long long)bn * CP + p] * stdv[bn] + mean[bn];
}

__global__ void aux_out_kernel(const float* __restrict__ mean, const float* __restrict__ stdv,
                               float* __restrict__ out)
{
    int i = blockIdx.x * blockDim.x + threadIdx.x;
    if (i >= CBN) return;
    out[CB * CP * CN + i] = mean[i];
    out[CB * CP * CN + CBN + i] = stdv[i];
}

// ---------------- host orchestration ----------------
static void launch_tc(const __half* A, const __half* B, float* C, const float* bias,
                      int M, int Nn, int Kd, int lda, int ldb,
                      long long ldcr, long long ldcc,
                      int batches, int bdiv,
                      long long sAh, long long sAl,
                      long long sBh, long long sBl,
                      long long sCh, long long sCl, int act)
{
    long long b128 = (long long)((M + 127) / 128) * ((Nn + 127) / 128) * batches;
    if (b128 >= 296) {
        dim3 grid((M + 127) / 128, (Nn + 127) / 128, batches);
        gemm_tc<128, 256, 3><<<grid, 256, SMEM_128>>>(A, B, C, bias, M, Nn, Kd, lda, ldb,
            ldcr, ldcc, bdiv, sAh, sAl, sBh, sBl, sCh, sCl, act);
    } else {
        dim3 grid((M + 63) / 64, (Nn + 127) / 128, batches);
        gemm_tc<64, 128, 2><<<grid, 128, SMEM_64>>>(A, B, C, bias, M, Nn, Kd, lda, ldb,
            ldcr, ldcc, bdiv, sAh, sAl, sBh, sBl, sCh, sCl, act);
    }
}

extern "C" void kernel_launch(void* const* d_in, const int* in_sizes, int n_in,
                              void* d_out, int out_size)
{
    (void)in_sizes; (void)n_in;
    const float* x_enc  = (const float*)d_in[0];
    const float* emb_W  = (const float*)d_in[1];
    const float* emb_b  = (const float*)d_in[2];
    const float* h0     = (const float*)d_in[3];
    const float* h1     = (const float*)d_in[4];
    const float* g0     = (const float*)d_in[5];
    const float* g1     = (const float*)d_in[6];
    const float* Wq     = (const float*)d_in[7];
    const float* bq     = (const float*)d_in[8];
    const float* Wk     = (const float*)d_in[9];
    const float* bk     = (const float*)d_in[10];
    const float* Wv     = (const float*)d_in[11];
    const float* bv     = (const float*)d_in[12];
    const float* Wo     = (const float*)d_in[13];
    const float* bo     = (const float*)d_in[14];
    const float* W1     = (const float*)d_in[15];
    const float* b1     = (const float*)d_in[16];
    const float* W2     = (const float*)d_in[17];
    const float* b2     = (const float*)d_in[18];
    const float* ln1_g  = (const float*)d_in[19];
    const float* ln1_b  = (const float*)d_in[20];
    const float* ln2_g  = (const float*)d_in[21];
    const float* ln2_b  = (const float*)d_in[22];
    const float* lnf_g  = (const float*)d_in[23];
    const float* lnf_b  = (const float*)d_in[24];
    const float* proj_W = (const float*)d_in[25];
    const float* proj_b = (const float*)d_in[26];

    cudaFuncSetAttribute(gemm_tc<128, 256, 3>, cudaFuncAttributeMaxDynamicSharedMemorySize, SMEM_128);
    cudaFuncSetAttribute(gemm_tc<64, 128, 2>,  cudaFuncAttributeMaxDynamicSharedMemorySize, SMEM_64);

    float* ws = nullptr;
    cudaGetSymbolAddress((void**)&ws, g_ws);
    __half* hw = nullptr;
    cudaGetSymbolAddress((void**)&hw, g_hws);

    float* h    = ws + O_H;
    float* mean = ws + O_MEAN;
    float* stdv = ws + O_STD;
    float* bqkv = ws + O_BQKV;
    float* dot  = ws + O_DOT;
    float* ao   = ws + O_AO;
    float* att  = ws + O_ATT;
    float* x1   = ws + O_X1;
    float* y2   = ws + O_Y2;
    float* dec  = ws + O_DEC;

    __half* xt_h  = hw + H_XT;
    __half* coefh = hw + H_COEF;
    __half* qkv   = hw + H_QKV;
    __half* qah   = hw + H_QA;
    __half* kah   = hw + H_KA;
    __half* prob  = hw + H_PROB;
    __half* rech  = hw + H_REC;
    __half* x1h   = hw + H_X1;
    __half* ffh   = hw + H_FF;
    __half* wts   = hw + H_WTS;
    __half* embWh = wts + W_EMB;
    __half* qkvWh = wts + W_QKV;
    __half* Woh   = wts + W_WO;
    __half* W1h   = wts + W_W1;
    __half* W2h   = wts + W_W2;
    __half* pWh   = wts + W_PW;

    // qn2/kn2 borrow the front of ao: softmax consumes them before AV writes ao
    float* qn2b = ao;
    float* kn2b = ao + (size_t)CB * 4 * CD;

    f2h_all<<<(int)((SEG7 + 255) / 256), 256>>>(emb_W, Wq, Wk, Wv, Wo, W1, W2, proj_W, wts);
    bias_concat<<<(2 * 3 * CD + 255) / 256, 256>>>(bq, bk, bv, bqkv);

    stats_kernel<<<CBN, 128>>>(x_enc, mean, stdv);
    {
        dim3 gn((CN + 31) / 32, CS / 32, CB), bn2(32, 8);
        norm_t_kernel<<<gn, bn2>>>(x_enc, mean, stdv, xt_h);
    }

    launch_tc(xt_h, embWh, h, emb_b, CBN, CD, CS, CS, CS, CD, 1,
              1, 1, 0, 0, 0, 0, 0, 0, 0);

    const long long ZAP = (long long)CD * KPAD;
    const long long ZD  = (long long)CD * CD;
    const long long BSTR = (long long)CN * 4 * CD;
    const long long QSTR = (long long)CN * 4 * 1536;

    for (int l = 0; l < 2; l++) {
        swt_dec_kernel<<<CBN, 256>>>(h, h0 + (long long)l * CN * 3, h1 + (long long)l * CN * 3, coefh);

        // fused QKV: one GEMM, N = 1536, fp16 out into qkv[b][n][m][1536]
        launch_tc(coefh, qkvWh + (long long)l * 3 * DD, (float*)qkv, bqkv + (long long)l * 3 * CD,
                  CBN * 4, 3 * CD, CD, CD, CD, 3 * CD, 1, 1, 1, 0, 0, 0, 0, 0, 0, 2);

        {
            dim3 g2(16, KPAD / 32, CB * 4), b2d(32, 8);
            trans_kernel<<<g2, b2d>>>(qkv,       qah, 1536);
            trans_kernel<<<g2, b2d>>>(qkv + 512, kah, 1536);
        }
        rowsq_kernel<<<CB * 4 * CD / 8, 256>>>(qah, qn2b);
        rowsq_kernel<<<CB * 4 * CD / 8, 256>>>(kah, kn2b);

        launch_tc(qah, kah, dot, nullptr, CD, CD, KPAD, KPAD, KPAD, CD, 1,
                  CB * 4, 1, ZAP, 0, ZAP, 0, ZD, 0, 0);

        score_softmax_kernel<<<CB * 4 * CD, 256>>>(dot, qn2b, kn2b, prob);

        // AV with V sliced from qkv (cols 1024..1535), scatter into coeffs layout
        launch_tc(prob, qkv + 1024, ao, nullptr, CD, CN, CD, CD, 4 * 1536, 1, 4 * CD,
                  CB * 4, 4,
                  4 * ZD, ZD,
                  QSTR, 1536,
                  BSTR, CD,
                  0);

        swt_rec_kernel<<<CBN, 256>>>(ao, g0 + (long long)l * CN * 3, g1 + (long long)l * CN * 3, rech);

        launch_tc(rech, Woh + (long long)l * DD, att, bo + (long long)l * CD,
                  CBN, CD, CD, CD, CD, CD, 1, 1, 1, 0, 0, 0, 0, 0, 0, 0);

        add_ln_kernel<<<CBN, 256>>>(h, att, ln1_g + (long long)l * CD, ln1_b + (long long)l * CD, x1, x1h);

        launch_tc(x1h, W1h + (long long)l * CDF * CD, (float*)ffh, b1 + (long long)l * CDF,
                  CBN, CDF, CD, CD, CD, CDF, 1, 1, 1, 0, 0, 0, 0, 0, 0, 3);
        launch_tc(ffh, W2h + (long long)l * CD * CDF, y2, b2 + (long long)l * CD,
                  CBN, CD, CDF, CDF, CDF, CD, 1, 1, 1, 0, 0, 0, 0, 0, 0, 0);

        add_ln_kernel<<<CBN, 256>>>(x1, y2, ln2_g + (long long)l * CD, ln2_b + (long long)l * CD, h, nullptr);
    }

    add_ln_kernel<<<CBN, 256>>>(h, nullptr, lnf_g, lnf_b, nullptr, x1h);
    launch_tc(x1h, pWh, dec, proj_b, CBN, CP, CD, CD, CD, CP, 1,
              1, 1, 0, 0, 0, 0, 0, 0, 0);

    out_kernel<<<(CB * CP * CN + 255) / 256, 256>>>(dec, mean, stdv, (float*)d_out);
    if (out_size >= CB * CP * CN + 2 * CBN) {
        aux_out_kernel<<<(CBN + 255) / 256, 256>>>(mean, stdv, (float*)d_out);
    }
}